// round 15
// baseline (speedup 1.0000x reference)
#include <cuda_runtime.h>
#include <cuda_bf16.h>
#include <cuda_fp16.h>
#include <cstdint>

#define IN_F   128
#define KGAUSS 4
#define OUT_F  32
#define KO     128   // KGAUSS * OUT_F

// node_feat scratch: [N][K*OUT_F] fp16
__device__ __half g_nf[100096 * 128];

// ---------------------------------------------------------------------------
// helpers
// ---------------------------------------------------------------------------
__device__ __forceinline__ uint32_t smem_u32(const void* p) {
    uint32_t a;
    asm("{ .reg .u64 t; cvta.to.shared.u64 t, %1; cvt.u32.u64 %0, t; }"
        : "=r"(a) : "l"(p));
    return a;
}
__device__ __forceinline__ unsigned pack_h2f(float a, float b) {
    __half2 h = __floats2half2_rn(a, b);
    return *reinterpret_cast<unsigned*>(&h);
}
__device__ __forceinline__ void ldsm4(uint32_t r[4], uint32_t addr) {
    asm volatile(
        "ldmatrix.sync.aligned.m8n8.x4.shared.b16 {%0,%1,%2,%3}, [%4];"
        : "=r"(r[0]), "=r"(r[1]), "=r"(r[2]), "=r"(r[3]) : "r"(addr));
}
__device__ __forceinline__ void mma_f16(float c[4], const uint32_t a[4],
                                        uint32_t b0, uint32_t b1) {
    asm volatile(
        "mma.sync.aligned.m16n8k16.row.col.f32.f16.f16.f32 "
        "{%0,%1,%2,%3}, {%4,%5,%6,%7}, {%8,%9}, {%0,%1,%2,%3};"
        : "+f"(c[0]), "+f"(c[1]), "+f"(c[2]), "+f"(c[3])
        : "r"(a[0]), "r"(a[1]), "r"(a[2]), "r"(a[3]), "r"(b0), "r"(b1));
}
__device__ __forceinline__ void cp_async16(uint32_t dst, const void* src) {
    asm volatile("cp.async.cg.shared.global [%0], [%1], 16;"
                 :: "r"(dst), "l"(src));
}

// smem layout:
//   [SM_W,   +34816)  W fp16, ldmatrix layout (stride TSTR=136 halfs)
//   [SM_A32, +65536)  A fp32 tile (row-major, 512B rows) -- cp.async target
//   A fp16 (34816B, ldmatrix layout) OVERLAYS SM_A32 after in-place convert
#define TSTR      136
#define TILE_B    (128 * TSTR * 2)       // 34816 B
#define SM_W      0
#define SM_A32    TILE_B
#define SM_A16    TILE_B                 // overlay
#define SM_TOTAL  (TILE_B + 65536)       // 100352 B -> 2 CTAs/SM

// ---------------------------------------------------------------------------
// GEMM via mma.sync fp16; A staged with cp.async (fp32) then converted
// in-place to fp16 ldmatrix layout. fp32 in, fp16 out.
// CTA: 128 rows x 128 cols. 8 warps = 4(M) x 2(N), warp tile 32x64.
// ---------------------------------------------------------------------------
extern "C" __global__ void __launch_bounds__(256, 2)
gmm_gemm_mma(const float* __restrict__ A, const float* __restrict__ W,
             __half* __restrict__ C, int N)
{
    extern __shared__ char smem[];
    const uint32_t sbase = smem_u32(smem);
    const int tid  = threadIdx.x;
    const int lane = tid & 31;
    const int wid  = tid >> 5;
    const int rowBase = blockIdx.x * 128;

    // ---- 1) queue the whole A tile via cp.async (fp32, row-major) ----
#pragma unroll
    for (int it = 0; it < 16; it++) {
        int idx = tid + it * 256;            // float4 index 0..4095
        int row = idx >> 5;
        int c4  = idx & 31;
        uint32_t dst = sbase + SM_A32 + (uint32_t)idx * 16u;
        int gr = rowBase + row;
        if (gr < N) {
            cp_async16(dst, &A[(size_t)gr * IN_F + c4 * 4]);
        } else {
            *(float4*)(smem + SM_A32 + (uint32_t)idx * 16u) =
                make_float4(0.f, 0.f, 0.f, 0.f);
        }
    }
    asm volatile("cp.async.commit_group;" ::: "memory");

    // ---- 2) stage W meanwhile (L2-resident after first CTAs) ----
#pragma unroll
    for (int it = 0; it < 16; it++) {
        int idx = tid + it * 256;
        int row = idx >> 5;
        int k0  = (idx & 31) * 4;
        float4 w = *(const float4*)&W[(size_t)row * IN_F + k0];
        *(uint2*)(smem + SM_W + (uint32_t)(row * TSTR + k0) * 2u) =
            make_uint2(pack_h2f(w.x, w.y), pack_h2f(w.z, w.w));
    }

    asm volatile("cp.async.wait_group 0;" ::: "memory");
    __syncthreads();

    // ---- 3) in-place convert: read own 16 float4s, sync, write fp16 ----
    float4 st[16];
#pragma unroll
    for (int it = 0; it < 16; it++) {
        int idx = tid + it * 256;
        st[it] = *(const float4*)(smem + SM_A32 + (uint32_t)idx * 16u);
    }
    __syncthreads();   // all reads done before overlay writes
#pragma unroll
    for (int it = 0; it < 16; it++) {
        int idx = tid + it * 256;
        int row = idx >> 5;
        int k0  = (idx & 31) * 4;
        *(uint2*)(smem + SM_A16 + (uint32_t)(row * TSTR + k0) * 2u) =
            make_uint2(pack_h2f(st[it].x, st[it].y),
                       pack_h2f(st[it].z, st[it].w));
    }
    __syncthreads();

    // ---- 4) MMA ----
    const int warp_m = wid & 3;
    const int warp_n = wid >> 2;

    float acc[2][8][4];
#pragma unroll
    for (int r = 0; r < 2; r++)
#pragma unroll
        for (int j = 0; j < 8; j++)
#pragma unroll
            for (int c = 0; c < 4; c++) acc[r][j][c] = 0.0f;

    const int a_row = warp_m * 32 + (lane & 15);
    const int a_kb  = (lane >> 4) * 8;
    const int b_mi  = lane >> 3;
    const int b_n   = warp_n * 64 + (b_mi & 1) * 8 + (lane & 7);
    const int b_kb  = (b_mi >> 1) * 8;

#pragma unroll
    for (int kk = 0; kk < 8; kk++) {
        const int k0 = kk * 16;
        uint32_t af[2][4];
#pragma unroll
        for (int r = 0; r < 2; r++) {
            uint32_t off = (uint32_t)((a_row + r * 16) * TSTR + k0 + a_kb) * 2u;
            ldsm4(af[r], sbase + SM_A16 + off);
        }
        uint32_t bf[4][4];
#pragma unroll
        for (int nf2 = 0; nf2 < 4; nf2++) {
            uint32_t off =
                (uint32_t)((b_n + nf2 * 16) * TSTR + k0 + b_kb) * 2u;
            ldsm4(bf[nf2], sbase + SM_W + off);
        }
#pragma unroll
        for (int r = 0; r < 2; r++) {
#pragma unroll
            for (int nf2 = 0; nf2 < 4; nf2++) {
                mma_f16(acc[r][nf2 * 2 + 0], af[r], bf[nf2][0], bf[nf2][2]);
                mma_f16(acc[r][nf2 * 2 + 1], af[r], bf[nf2][1], bf[nf2][3]);
            }
        }
    }

    // ---- 5) epilogue ----
#pragma unroll
    for (int r = 0; r < 2; r++) {
        int gr0 = rowBase + warp_m * 32 + r * 16 + (lane >> 2);
#pragma unroll
        for (int j = 0; j < 8; j++) {
            int col = warp_n * 64 + j * 8 + (lane & 3) * 2;
            if (gr0 < N) {
                __half2 h = __floats2half2_rn(acc[r][j][0], acc[r][j][1]);
                *(__half2*)&C[(size_t)gr0 * KO + col] = h;
            }
            if (gr0 + 8 < N) {
                __half2 h = __floats2half2_rn(acc[r][j][2], acc[r][j][3]);
                *(__half2*)&C[(size_t)(gr0 + 8) * KO + col] = h;
            }
        }
    }
}

// ---------------------------------------------------------------------------
// Edge phase (round-8 version, best measured): persistent grid, one warp =
// two nodes, depth-2 pipeline on metadata, inline weights.
// ---------------------------------------------------------------------------
#define EDGE_BLOCKS 592   // 4 CTAs/SM on 148 SMs, one wave

extern "C" __global__ void __launch_bounds__(256, 4)
gmm_edge_kernel(const int* __restrict__ rowptr, const int* __restrict__ colind,
                const int* __restrict__ permute, const float* __restrict__ pseudo,
                const float* __restrict__ mu, const float* __restrict__ inv_sigma,
                const float* __restrict__ bias, const __half* __restrict__ NF,
                float* __restrict__ out, int N)
{
    __shared__ uint2  s_pack[8][2][16][4];   // [warp][half][edge][k] = (src, w)
    __shared__ float4 s_gp[4];               // (mu.x, mu.y, is.x, is.y) per k

    const unsigned FULL = 0xffffffffu;
    const int lane  = threadIdx.x & 31;
    const int wrp   = threadIdx.x >> 5;
    const int hn    = lane >> 4;        // which node of the pair
    const int hl    = lane & 15;        // lane within half
    const int gwarp = (blockIdx.x * blockDim.x + threadIdx.x) >> 5;
    const int nwarp = (gridDim.x * blockDim.x) >> 5;
    const int kq    = hl >> 2;          // k this lane gathers

    if (threadIdx.x < 4) {
        s_gp[threadIdx.x] = make_float4(mu[2 * threadIdx.x],
                                        mu[2 * threadIdx.x + 1],
                                        inv_sigma[2 * threadIdx.x],
                                        inv_sigma[2 * threadIdx.x + 1]);
    }
    __syncthreads();

    float4 b0 = make_float4(0.f, 0.f, 0.f, 0.f);
    float4 b1 = make_float4(0.f, 0.f, 0.f, 0.f);
    if (hl < 4) {
        b0 = *(const float4*)&bias[hl * 8];
        b1 = *(const float4*)&bias[hl * 8 + 4];
    }

    const float2* pseudo2 = (const float2*)pseudo;
    const int npairs = (N + 1) >> 1;

    auto load_meta = [&](int pp, int& e0o, int& dego, int& srco, int& pio) {
        e0o = 0; dego = 0; srco = 0; pio = 0;
        int nd = 2 * pp + hn;
        if (pp < npairs && nd < N) {
            int a = rowptr[nd];
            int b = rowptr[nd + 1];
            e0o = a;
            dego = b - a;
            int cap = dego < 16 ? dego : 16;
            if (hl < cap) {
                srco = colind[a + hl];
                pio  = permute[a + hl];
            }
        }
    };

    // ---- pipeline prologue ----
    int p = gwarp;
    int e0_c, deg_c, src_c, pi_c;
    int e0_n, deg_n, src_n, pi_n;
    float2 pp_c = make_float2(0.f, 0.f);
    load_meta(p, e0_c, deg_c, src_c, pi_c);
    if (hl < (deg_c < 16 ? deg_c : 16)) pp_c = pseudo2[pi_c];
    load_meta(p + nwarp, e0_n, deg_n, src_n, pi_n);

    for (; p < npairs; p += nwarp) {
        const int node  = 2 * p + hn;
        const bool valid = node < N;
        const int cnt = deg_c < 16 ? deg_c : 16;

        // ---- pack current pair's weights ----
        if (hl < cnt) {
#pragma unroll
            for (int k = 0; k < 4; k++) {
                float4 g = s_gp[k];
                float d0 = (pp_c.x - g.x) * g.z;
                float d1 = (pp_c.y - g.y) * g.w;
                float w  = __expf(-0.5f * (d0 * d0 + d1 * d1));
                s_pack[wrp][hn][hl][k] =
                    make_uint2((unsigned)src_c, __float_as_uint(w));
            }
        }

        // ---- prefetch: pseudo for p+1, meta for p+2 ----
        float2 pp_n = make_float2(0.f, 0.f);
        if (hl < (deg_n < 16 ? deg_n : 16)) pp_n = pseudo2[pi_n];
        int e0_2, deg_2, src_2, pi_2;
        load_meta(p + 2 * nwarp, e0_2, deg_2, src_2, pi_2);

        __syncwarp(FULL);

        // ---- gather current pair ----
        float acc[8];
#pragma unroll
        for (int j = 0; j < 8; j++) acc[j] = 0.0f;

        if (cnt == 16) {
#pragma unroll
            for (int e = 0; e < 16; e++) {
                uint2 pk = s_pack[wrp][hn][e][kq];
                float w  = __uint_as_float(pk.y);
                uint4 v  = ((const uint4*)(NF + (size_t)pk.x * KO))[hl];
                float2 f0 = __half22float2(*reinterpret_cast<__half2*>(&v.x));
                float2 f1 = __half22float2(*reinterpret_cast<__half2*>(&v.y));
                float2 f2 = __half22float2(*reinterpret_cast<__half2*>(&v.z));
                float2 f3 = __half22float2(*reinterpret_cast<__half2*>(&v.w));
                acc[0] += w * f0.x;  acc[1] += w * f0.y;
                acc[2] += w * f1.x;  acc[3] += w * f1.y;
                acc[4] += w * f2.x;  acc[5] += w * f2.y;
                acc[6] += w * f3.x;  acc[7] += w * f3.y;
            }
        } else {
            for (int e = 0; e < cnt; e++) {
                uint2 pk = s_pack[wrp][hn][e][kq];
                float w  = __uint_as_float(pk.y);
                uint4 v  = ((const uint4*)(NF + (size_t)pk.x * KO))[hl];
                float2 f0 = __half22float2(*reinterpret_cast<__half2*>(&v.x));
                float2 f1 = __half22float2(*reinterpret_cast<__half2*>(&v.y));
                float2 f2 = __half22float2(*reinterpret_cast<__half2*>(&v.z));
                float2 f3 = __half22float2(*reinterpret_cast<__half2*>(&v.w));
                acc[0] += w * f0.x;  acc[1] += w * f0.y;
                acc[2] += w * f1.x;  acc[3] += w * f1.y;
                acc[4] += w * f2.x;  acc[5] += w * f2.y;
                acc[6] += w * f3.x;  acc[7] += w * f3.y;
            }
        }

        // ---- rare fallback: degree > 16 (not pipelined) ----
        if (__any_sync(FULL, deg_c > 16)) {
            float4 gq = s_gp[kq];
            for (int e = e0_c + 16; e < e0_c + deg_c; e++) {
                int src = colind[e];
                int pi  = permute[e];
                float2 pp = pseudo2[pi];
                float d0 = (pp.x - gq.x) * gq.z;
                float d1 = (pp.y - gq.y) * gq.w;
                float w  = __expf(-0.5f * (d0 * d0 + d1 * d1));
                uint4 v  = ((const uint4*)(NF + (size_t)src * KO))[hl];
                float2 f0 = __half22float2(*reinterpret_cast<__half2*>(&v.x));
                float2 f1 = __half22float2(*reinterpret_cast<__half2*>(&v.y));
                float2 f2 = __half22float2(*reinterpret_cast<__half2*>(&v.z));
                float2 f3 = __half22float2(*reinterpret_cast<__half2*>(&v.w));
                acc[0] += w * f0.x;  acc[1] += w * f0.y;
                acc[2] += w * f1.x;  acc[3] += w * f1.y;
                acc[4] += w * f2.x;  acc[5] += w * f2.y;
                acc[6] += w * f3.x;  acc[7] += w * f3.y;
            }
        }

        // ---- reduce over k (lane bits 2,3 of hl) ----
#pragma unroll
        for (int j = 0; j < 8; j++) {
            acc[j] += __shfl_xor_sync(FULL, acc[j], 4);
            acc[j] += __shfl_xor_sync(FULL, acc[j], 8);
        }

        if (hl < 4 && valid) {
            float* dst = out + (size_t)node * OUT_F + hl * 8;
            *(float4*)dst = make_float4(acc[0] + b0.x, acc[1] + b0.y,
                                        acc[2] + b0.z, acc[3] + b0.w);
            *(float4*)(dst + 4) = make_float4(acc[4] + b1.x, acc[5] + b1.y,
                                              acc[6] + b1.z, acc[7] + b1.w);
        }

        __syncwarp(FULL);   // protect s_pack before next pack overwrites

        // ---- rotate pipeline ----
        e0_c = e0_n; deg_c = deg_n; src_c = src_n; pp_c = pp_n;
        e0_n = e0_2; deg_n = deg_2; src_n = src_2; pi_n = pi_2;
    }
}

// ---------------------------------------------------------------------------
// Inputs (metadata order):
//  0 rowptr[N+1] i32, 1 colind[E] i32, 2 colptr i32, 3 rowind i32,
//  4 permute[E] i32, 5 feat[N*128] f32, 6 pseudo[E*2] f32,
//  7 fc_w[128*128] f32, 8 mu[4*2] f32, 9 inv_sigma[4*2] f32, 10 bias[32] f32
// ---------------------------------------------------------------------------
extern "C" void kernel_launch(void* const* d_in, const int* in_sizes, int n_in,
                              void* d_out, int out_size)
{
    const int*   rowptr    = (const int*)  d_in[0];
    const int*   colind    = (const int*)  d_in[1];
    const int*   permute   = (const int*)  d_in[4];
    const float* feat      = (const float*)d_in[5];
    const float* pseudo    = (const float*)d_in[6];
    const float* fc_w      = (const float*)d_in[7];
    const float* mu        = (const float*)d_in[8];
    const float* inv_sigma = (const float*)d_in[9];
    const float* bias      = (const float*)d_in[10];

    const int N = in_sizes[5] / IN_F;

    __half* nf;
    cudaGetSymbolAddress((void**)&nf, g_nf);

    cudaFuncSetAttribute(gmm_gemm_mma,
                         cudaFuncAttributeMaxDynamicSharedMemorySize, SM_TOTAL);
    const int gemm_blocks = (N + 127) / 128;
    gmm_gemm_mma<<<gemm_blocks, 256, SM_TOTAL>>>(feat, fc_w, nf, N);

    gmm_edge_kernel<<<EDGE_BLOCKS, 256>>>(rowptr, colind, permute, pseudo,
                                          mu, inv_sigma, bias, nf,
                                          (float*)d_out, N);
}

// round 16
// speedup vs baseline: 1.5056x; 1.5056x over previous
#include <cuda_runtime.h>
#include <cuda_bf16.h>
#include <cuda_fp16.h>
#include <cstdint>

#define IN_F   128
#define KGAUSS 4
#define OUT_F  32
#define KO     128   // KGAUSS * OUT_F

// node_feat scratch: [N][K*OUT_F] fp16
__device__ __half g_nf[100096 * 128];

// ---------------------------------------------------------------------------
// helpers
// ---------------------------------------------------------------------------
__device__ __forceinline__ uint32_t smem_u32(const void* p) {
    uint32_t a;
    asm("{ .reg .u64 t; cvta.to.shared.u64 t, %1; cvt.u32.u64 %0, t; }"
        : "=r"(a) : "l"(p));
    return a;
}
__device__ __forceinline__ unsigned pack_h2f(float a, float b) {
    __half2 h = __floats2half2_rn(a, b);
    return *reinterpret_cast<unsigned*>(&h);
}
__device__ __forceinline__ void ldsm4(uint32_t r[4], uint32_t addr) {
    asm volatile(
        "ldmatrix.sync.aligned.m8n8.x4.shared.b16 {%0,%1,%2,%3}, [%4];"
        : "=r"(r[0]), "=r"(r[1]), "=r"(r[2]), "=r"(r[3]) : "r"(addr));
}
__device__ __forceinline__ void mma_f16(float c[4], const uint32_t a[4],
                                        uint32_t b0, uint32_t b1) {
    asm volatile(
        "mma.sync.aligned.m16n8k16.row.col.f32.f16.f16.f32 "
        "{%0,%1,%2,%3}, {%4,%5,%6,%7}, {%8,%9}, {%0,%1,%2,%3};"
        : "+f"(c[0]), "+f"(c[1]), "+f"(c[2]), "+f"(c[3])
        : "r"(a[0]), "r"(a[1]), "r"(a[2]), "r"(a[3]), "r"(b0), "r"(b1));
}
__device__ __forceinline__ void cp_async16(uint32_t dst, const void* src) {
    asm volatile("cp.async.cg.shared.global [%0], [%1], 16;"
                 :: "r"(dst), "l"(src));
}

// smem layout:
//   [SM_W,   +34816)  W fp16, ldmatrix layout (stride TSTR=136 halfs)
//   [SM_A16, +34816)  A fp16, ldmatrix layout
//   [SM_A32, +32768)  A fp32 HALF tile (k-range of 64) -- cp.async target
#define TSTR      136
#define TILE_B    (128 * TSTR * 2)       // 34816 B
#define SM_W      0
#define SM_A16    TILE_B
#define SM_A32    (2 * TILE_B)
#define SM_TOTAL  (2 * TILE_B + 32768)   // 102400 B -> 2 CTAs/SM

// ---------------------------------------------------------------------------
// GEMM via mma.sync fp16. A staged in two k-halves with cp.async; the second
// half's DMA overlaps the first half's MMA. fp32 in, fp16 out.
// CTA: 128 rows x 128 cols. 8 warps = 4(M) x 2(N), warp tile 32x64.
// ---------------------------------------------------------------------------
extern "C" __global__ void __launch_bounds__(256, 2)
gmm_gemm_mma(const float* __restrict__ A, const float* __restrict__ W,
             __half* __restrict__ C, int N)
{
    extern __shared__ char smem[];
    const uint32_t sbase = smem_u32(smem);
    const int tid  = threadIdx.x;
    const int lane = tid & 31;
    const int wid  = tid >> 5;
    const int rowBase = blockIdx.x * 128;

    // queue one k-half (64 cols, 32 KB) of the A tile via cp.async
    auto cpHalf = [&](int kh) {
#pragma unroll
        for (int it = 0; it < 8; it++) {
            int idx = tid + it * 256;          // float4 idx 0..2047
            int row = idx >> 4;                // 16 float4s per row-half
            int c4  = idx & 15;
            uint32_t dst = sbase + SM_A32 + (uint32_t)idx * 16u;
            int gr = rowBase + row;
            if (gr < N) {
                cp_async16(dst, &A[(size_t)gr * IN_F + kh * 64 + c4 * 4]);
            } else {
                *(float4*)(smem + SM_A32 + (uint32_t)idx * 16u) =
                    make_float4(0.f, 0.f, 0.f, 0.f);
            }
        }
        asm volatile("cp.async.commit_group;" ::: "memory");
    };
    // wait own copies, convert own float4s to fp16 ldmatrix layout.
    // Each thread reads exactly the addresses it copied -> wait_group 0 is
    // sufficient, no block sync needed here.
    auto cvtHalf = [&](int kh) {
        asm volatile("cp.async.wait_group 0;" ::: "memory");
#pragma unroll
        for (int it = 0; it < 8; it++) {
            int idx = tid + it * 256;
            int row = idx >> 4;
            int c4  = idx & 15;
            float4 v = *(const float4*)(smem + SM_A32 + (uint32_t)idx * 16u);
            int k0 = kh * 64 + c4 * 4;
            *(uint2*)(smem + SM_A16 + (uint32_t)(row * TSTR + k0) * 2u) =
                make_uint2(pack_h2f(v.x, v.y), pack_h2f(v.z, v.w));
        }
    };

    // ---- pipeline ----
    cpHalf(0);                               // DMA half1

    // stage W under half1's DMA latency
#pragma unroll
    for (int it = 0; it < 16; it++) {
        int idx = tid + it * 256;
        int row = idx >> 5;
        int k0  = (idx & 31) * 4;
        float4 w = *(const float4*)&W[(size_t)row * IN_F + k0];
        *(uint2*)(smem + SM_W + (uint32_t)(row * TSTR + k0) * 2u) =
            make_uint2(pack_h2f(w.x, w.y), pack_h2f(w.z, w.w));
    }

    cvtHalf(0);                              // own-thread wait + convert
    cpHalf(1);                               // DMA half2 (overlaps MMA below)
    __syncthreads();                         // W + A16-half1 visible to all

    const int warp_m = wid & 3;
    const int warp_n = wid >> 2;

    float acc[2][8][4];
#pragma unroll
    for (int r = 0; r < 2; r++)
#pragma unroll
        for (int j = 0; j < 8; j++)
#pragma unroll
            for (int c = 0; c < 4; c++) acc[r][j][c] = 0.0f;

    const int a_row = warp_m * 32 + (lane & 15);
    const int a_kb  = (lane >> 4) * 8;
    const int b_mi  = lane >> 3;
    const int b_n   = warp_n * 64 + (b_mi & 1) * 8 + (lane & 7);
    const int b_kb  = (b_mi >> 1) * 8;

    auto mmaQuad = [&](int khStart) {
#pragma unroll
        for (int kk = khStart; kk < khStart + 4; kk++) {
            const int k0 = kk * 16;
            uint32_t af[2][4];
#pragma unroll
            for (int r = 0; r < 2; r++) {
                uint32_t off =
                    (uint32_t)((a_row + r * 16) * TSTR + k0 + a_kb) * 2u;
                ldsm4(af[r], sbase + SM_A16 + off);
            }
            uint32_t bf[4][4];
#pragma unroll
            for (int nf2 = 0; nf2 < 4; nf2++) {
                uint32_t off =
                    (uint32_t)((b_n + nf2 * 16) * TSTR + k0 + b_kb) * 2u;
                ldsm4(bf[nf2], sbase + SM_W + off);
            }
#pragma unroll
            for (int r = 0; r < 2; r++) {
#pragma unroll
                for (int nf2 = 0; nf2 < 4; nf2++) {
                    mma_f16(acc[r][nf2 * 2 + 0], af[r], bf[nf2][0], bf[nf2][2]);
                    mma_f16(acc[r][nf2 * 2 + 1], af[r], bf[nf2][1], bf[nf2][3]);
                }
            }
        }
    };

    mmaQuad(0);                              // overlaps half2 DMA
    cvtHalf(1);                              // own-thread wait + convert
    __syncthreads();                         // A16-half2 visible to all
    mmaQuad(4);

    // ---- epilogue ----
#pragma unroll
    for (int r = 0; r < 2; r++) {
        int gr0 = rowBase + warp_m * 32 + r * 16 + (lane >> 2);
#pragma unroll
        for (int j = 0; j < 8; j++) {
            int col = warp_n * 64 + j * 8 + (lane & 3) * 2;
            if (gr0 < N) {
                __half2 h = __floats2half2_rn(acc[r][j][0], acc[r][j][1]);
                *(__half2*)&C[(size_t)gr0 * KO + col] = h;
            }
            if (gr0 + 8 < N) {
                __half2 h = __floats2half2_rn(acc[r][j][2], acc[r][j][3]);
                *(__half2*)&C[(size_t)(gr0 + 8) * KO + col] = h;
            }
        }
    }
}

// ---------------------------------------------------------------------------
// Edge phase (round-8 version, best measured 41.2us): persistent grid, one
// warp = two nodes, depth-2 pipeline on metadata, inline weights.
// ---------------------------------------------------------------------------
#define EDGE_BLOCKS 592   // 4 CTAs/SM on 148 SMs, one wave

extern "C" __global__ void __launch_bounds__(256, 4)
gmm_edge_kernel(const int* __restrict__ rowptr, const int* __restrict__ colind,
                const int* __restrict__ permute, const float* __restrict__ pseudo,
                const float* __restrict__ mu, const float* __restrict__ inv_sigma,
                const float* __restrict__ bias, const __half* __restrict__ NF,
                float* __restrict__ out, int N)
{
    __shared__ uint2  s_pack[8][2][16][4];   // [warp][half][edge][k] = (src, w)
    __shared__ float4 s_gp[4];               // (mu.x, mu.y, is.x, is.y) per k

    const unsigned FULL = 0xffffffffu;
    const int lane  = threadIdx.x & 31;
    const int wrp   = threadIdx.x >> 5;
    const int hn    = lane >> 4;        // which node of the pair
    const int hl    = lane & 15;        // lane within half
    const int gwarp = (blockIdx.x * blockDim.x + threadIdx.x) >> 5;
    const int nwarp = (gridDim.x * blockDim.x) >> 5;
    const int kq    = hl >> 2;          // k this lane gathers

    if (threadIdx.x < 4) {
        s_gp[threadIdx.x] = make_float4(mu[2 * threadIdx.x],
                                        mu[2 * threadIdx.x + 1],
                                        inv_sigma[2 * threadIdx.x],
                                        inv_sigma[2 * threadIdx.x + 1]);
    }
    __syncthreads();

    float4 b0 = make_float4(0.f, 0.f, 0.f, 0.f);
    float4 b1 = make_float4(0.f, 0.f, 0.f, 0.f);
    if (hl < 4) {
        b0 = *(const float4*)&bias[hl * 8];
        b1 = *(const float4*)&bias[hl * 8 + 4];
    }

    const float2* pseudo2 = (const float2*)pseudo;
    const int npairs = (N + 1) >> 1;

    auto load_meta = [&](int pp, int& e0o, int& dego, int& srco, int& pio) {
        e0o = 0; dego = 0; srco = 0; pio = 0;
        int nd = 2 * pp + hn;
        if (pp < npairs && nd < N) {
            int a = rowptr[nd];
            int b = rowptr[nd + 1];
            e0o = a;
            dego = b - a;
            int cap = dego < 16 ? dego : 16;
            if (hl < cap) {
                srco = colind[a + hl];
                pio  = permute[a + hl];
            }
        }
    };

    // ---- pipeline prologue ----
    int p = gwarp;
    int e0_c, deg_c, src_c, pi_c;
    int e0_n, deg_n, src_n, pi_n;
    float2 pp_c = make_float2(0.f, 0.f);
    load_meta(p, e0_c, deg_c, src_c, pi_c);
    if (hl < (deg_c < 16 ? deg_c : 16)) pp_c = pseudo2[pi_c];
    load_meta(p + nwarp, e0_n, deg_n, src_n, pi_n);

    for (; p < npairs; p += nwarp) {
        const int node  = 2 * p + hn;
        const bool valid = node < N;
        const int cnt = deg_c < 16 ? deg_c : 16;

        // ---- pack current pair's weights ----
        if (hl < cnt) {
#pragma unroll
            for (int k = 0; k < 4; k++) {
                float4 g = s_gp[k];
                float d0 = (pp_c.x - g.x) * g.z;
                float d1 = (pp_c.y - g.y) * g.w;
                float w  = __expf(-0.5f * (d0 * d0 + d1 * d1));
                s_pack[wrp][hn][hl][k] =
                    make_uint2((unsigned)src_c, __float_as_uint(w));
            }
        }

        // ---- prefetch: pseudo for p+1, meta for p+2 ----
        float2 pp_n = make_float2(0.f, 0.f);
        if (hl < (deg_n < 16 ? deg_n : 16)) pp_n = pseudo2[pi_n];
        int e0_2, deg_2, src_2, pi_2;
        load_meta(p + 2 * nwarp, e0_2, deg_2, src_2, pi_2);

        __syncwarp(FULL);

        // ---- gather current pair ----
        float acc[8];
#pragma unroll
        for (int j = 0; j < 8; j++) acc[j] = 0.0f;

        if (cnt == 16) {
#pragma unroll
            for (int e = 0; e < 16; e++) {
                uint2 pk = s_pack[wrp][hn][e][kq];
                float w  = __uint_as_float(pk.y);
                uint4 v  = ((const uint4*)(NF + (size_t)pk.x * KO))[hl];
                float2 f0 = __half22float2(*reinterpret_cast<__half2*>(&v.x));
                float2 f1 = __half22float2(*reinterpret_cast<__half2*>(&v.y));
                float2 f2 = __half22float2(*reinterpret_cast<__half2*>(&v.z));
                float2 f3 = __half22float2(*reinterpret_cast<__half2*>(&v.w));
                acc[0] += w * f0.x;  acc[1] += w * f0.y;
                acc[2] += w * f1.x;  acc[3] += w * f1.y;
                acc[4] += w * f2.x;  acc[5] += w * f2.y;
                acc[6] += w * f3.x;  acc[7] += w * f3.y;
            }
        } else {
            for (int e = 0; e < cnt; e++) {
                uint2 pk = s_pack[wrp][hn][e][kq];
                float w  = __uint_as_float(pk.y);
                uint4 v  = ((const uint4*)(NF + (size_t)pk.x * KO))[hl];
                float2 f0 = __half22float2(*reinterpret_cast<__half2*>(&v.x));
                float2 f1 = __half22float2(*reinterpret_cast<__half2*>(&v.y));
                float2 f2 = __half22float2(*reinterpret_cast<__half2*>(&v.z));
                float2 f3 = __half22float2(*reinterpret_cast<__half2*>(&v.w));
                acc[0] += w * f0.x;  acc[1] += w * f0.y;
                acc[2] += w * f1.x;  acc[3] += w * f1.y;
                acc[4] += w * f2.x;  acc[5] += w * f2.y;
                acc[6] += w * f3.x;  acc[7] += w * f3.y;
            }
        }

        // ---- rare fallback: degree > 16 (not pipelined) ----
        if (__any_sync(FULL, deg_c > 16)) {
            float4 gq = s_gp[kq];
            for (int e = e0_c + 16; e < e0_c + deg_c; e++) {
                int src = colind[e];
                int pi  = permute[e];
                float2 pp = pseudo2[pi];
                float d0 = (pp.x - gq.x) * gq.z;
                float d1 = (pp.y - gq.y) * gq.w;
                float w  = __expf(-0.5f * (d0 * d0 + d1 * d1));
                uint4 v  = ((const uint4*)(NF + (size_t)src * KO))[hl];
                float2 f0 = __half22float2(*reinterpret_cast<__half2*>(&v.x));
                float2 f1 = __half22float2(*reinterpret_cast<__half2*>(&v.y));
                float2 f2 = __half22float2(*reinterpret_cast<__half2*>(&v.z));
                float2 f3 = __half22float2(*reinterpret_cast<__half2*>(&v.w));
                acc[0] += w * f0.x;  acc[1] += w * f0.y;
                acc[2] += w * f1.x;  acc[3] += w * f1.y;
                acc[4] += w * f2.x;  acc[5] += w * f2.y;
                acc[6] += w * f3.x;  acc[7] += w * f3.y;
            }
        }

        // ---- reduce over k (lane bits 2,3 of hl) ----
#pragma unroll
        for (int j = 0; j < 8; j++) {
            acc[j] += __shfl_xor_sync(FULL, acc[j], 4);
            acc[j] += __shfl_xor_sync(FULL, acc[j], 8);
        }

        if (hl < 4 && valid) {
            float* dst = out + (size_t)node * OUT_F + hl * 8;
            *(float4*)dst = make_float4(acc[0] + b0.x, acc[1] + b0.y,
                                        acc[2] + b0.z, acc[3] + b0.w);
            *(float4*)(dst + 4) = make_float4(acc[4] + b1.x, acc[5] + b1.y,
                                              acc[6] + b1.z, acc[7] + b1.w);
        }

        __syncwarp(FULL);   // protect s_pack before next pack overwrites

        // ---- rotate pipeline ----
        e0_c = e0_n; deg_c = deg_n; src_c = src_n; pp_c = pp_n;
        e0_n = e0_2; deg_n = deg_2; src_n = src_2; pi_n = pi_2;
    }
}

// ---------------------------------------------------------------------------
// Inputs (metadata order):
//  0 rowptr[N+1] i32, 1 colind[E] i32, 2 colptr i32, 3 rowind i32,
//  4 permute[E] i32, 5 feat[N*128] f32, 6 pseudo[E*2] f32,
//  7 fc_w[128*128] f32, 8 mu[4*2] f32, 9 inv_sigma[4*2] f32, 10 bias[32] f32
// ---------------------------------------------------------------------------
extern "C" void kernel_launch(void* const* d_in, const int* in_sizes, int n_in,
                              void* d_out, int out_size)
{
    const int*   rowptr    = (const int*)  d_in[0];
    const int*   colind    = (const int*)  d_in[1];
    const int*   permute   = (const int*)  d_in[4];
    const float* feat      = (const float*)d_in[5];
    const float* pseudo    = (const float*)d_in[6];
    const float* fc_w      = (const float*)d_in[7];
    const float* mu        = (const float*)d_in[8];
    const float* inv_sigma = (const float*)d_in[9];
    const float* bias      = (const float*)d_in[10];

    const int N = in_sizes[5] / IN_F;

    __half* nf;
    cudaGetSymbolAddress((void**)&nf, g_nf);

    cudaFuncSetAttribute(gmm_gemm_mma,
                         cudaFuncAttributeMaxDynamicSharedMemorySize, SM_TOTAL);
    const int gemm_blocks = (N + 127) / 128;
    gmm_gemm_mma<<<gemm_blocks, 256, SM_TOTAL>>>(feat, fc_w, nf, N);

    gmm_edge_kernel<<<EDGE_BLOCKS, 256>>>(rowptr, colind, permute, pseudo,
                                          mu, inv_sigma, bias, nf,
                                          (float*)d_out, N);
}